// round 15
// baseline (speedup 1.0000x reference)
#include <cuda_runtime.h>
#include <math.h>

#define NB    8192
#define GRID  32
#define NT    1024
#define RPB   256
#define CHK   256
#define TPAD  257

__device__ __align__(16) float g_tsrt[NB];
__device__ __align__(16) float g_pe[NB];
__device__ float g_nll[GRID];
__device__ float g_per[GRID];
__device__ int   g_cnt[GRID];
__device__ int   g_ticket;
__device__ unsigned g_bcount;
__device__ volatile unsigned g_bgen;

#define BAR256() asm volatile("bar.sync 1, 256;" ::: "memory")

__device__ __forceinline__ void grid_bar() {
    __threadfence();
    __syncthreads();
    if (threadIdx.x == 0) {
        unsigned gen = g_bgen;
        if (atomicAdd(&g_bcount, 1u) == GRID - 1) {
            g_bcount = 0;
            __threadfence();
            g_bgen = gen + 1;
        } else {
            while (g_bgen == gen) {}
        }
        __threadfence();
    }
    __syncthreads();
}

extern "C" __global__ void __launch_bounds__(NT, 1)
surv_one_kernel(const float* __restrict__ outputs,
                const int* __restrict__ y,
                const float* __restrict__ t,
                const int* __restrict__ c,
                float* __restrict__ out)
{
    __shared__ __align__(16) char sbuf[43136];
    float* se     = (float*)(sbuf);            // [256]   (phase A/B only)
    float* srisk  = (float*)(sbuf + 1024);     // [256]   (phase A/B only)
    int*   sc     = (int*)  (sbuf + 2048);     // [256]   (phase A/B only)
    int*   sidx   = (int*)  (sbuf + 3072);     // [256]   (phase A/B only)
    float* st_s   = (float*)(sbuf + 4096);     // [256] sorted t
    float* sval_s = (float*)(sbuf + 5120);     // [256] (c==0)?risk:+1, sorted order
    // sort temps @6144 (overlap t_tab; sort done before phase C)
    float* tt     = (float*)(sbuf + 6144);
    int*   ii     = (int*)  (sbuf + 7168);
    int*   hist   = (int*)  (sbuf + 8192);
    int*   cursor = (int*)  (sbuf + 9216);
    int*   start  = (int*)  (sbuf + 10240);
    // phase-C global t table, padded stride [32*257*4 = 32896 B] @6144..39040
    float* t_tab  = (float*)(sbuf + 6144);
    // phase-C per-query partials
    float* sq_sum = (float*)(sbuf);            // [1024] overlaps se..sidx (dead in C)
    int*   sq_cnt = (int*)  (sbuf + 39040);    // [1024]
    __shared__ float wpart[8];
    __shared__ float bredf[32];
    __shared__ int   bredi[32];

    const int tid  = threadIdx.x;
    const int blk  = blockIdx.x;
    const int lane = tid & 31;
    const int wid  = tid >> 5;

    // ================= Phase A + B: first 8 warps only =================
    if (tid < RPB) {
        const int r = blk * RPB + tid;

        // ---- collapsed row math (exact rewrite of reference NLL/risk) ----
        float4 o4 = ((const float4*)outputs)[r];
        float a0 = __expf(o4.x), a1 = __expf(o4.y);
        float a2 = __expf(o4.z), a3 = __expf(o4.w);
        float v3   = 1.f + a3;
        float v23  = (1.f + a2) * v3;
        float v123 = (1.f + a1) * v23;
        float Q    = v123 + v23 + v3 + 1.f;
        float h0 = 1.f + a0;
        float h1 = h0 * (1.f + a1);
        float h2 = h1 * (1.f + a2);
        float h3 = h0 * v123;
        float risk = -__fdividef(Q, h3);

        int yi = y[r];
        float Py = (yi == 0) ? h0 : (yi == 1) ? h1 : (yi == 2) ? h2 : h3;
        float oy = (yi == 0) ? o4.x : (yi == 1) ? o4.y : (yi == 2) ? o4.z : o4.w;
        float cf = (float)c[r];
        float nll = __logf(Py) - (1.f - cf) * oy;

        se[tid]    = __expf(risk);
        srisk[tid] = risk;
        sc[tid]    = c[r];
        float tv   = t[r];

        #pragma unroll
        for (int off = 16; off > 0; off >>= 1)
            nll += __shfl_xor_sync(0xffffffffu, nll, off);
        if (lane == 0) wpart[wid] = nll;

        // ---- deterministic bucket sort (t uniform [0,1)) ----
        int b = 255 - min(255, max(0, (int)(tv * 256.0f)));
        hist[tid]   = 0;
        cursor[tid] = 0;
        BAR256();
        atomicAdd(&hist[b], 1);
        BAR256();
        if (tid == 0) {                      // NLL partial (wpart complete)
            float s = 0.f;
            #pragma unroll
            for (int w = 0; w < 8; w++) s += wpart[w];
            g_nll[blk] = s;
        }
        if (wid == 0) {                      // scan 256 counts -> start[]
            int h[8];
            #pragma unroll
            for (int i = 0; i < 8; i++) h[i] = hist[lane * 8 + i];
            #pragma unroll
            for (int i = 1; i < 8; i++) h[i] += h[i - 1];
            int v = h[7];
            #pragma unroll
            for (int off = 1; off < 32; off <<= 1) {
                int n = __shfl_up_sync(0xffffffffu, v, off);
                if (lane >= off) v += n;
            }
            int excl = __shfl_up_sync(0xffffffffu, v, 1);
            if (lane == 0) excl = 0;
            start[lane * 8] = excl;
            #pragma unroll
            for (int i = 1; i < 8; i++) start[lane * 8 + i] = excl + h[i - 1];
        }
        BAR256();
        int slot = atomicAdd(&cursor[b], 1);     // nondet order, det membership
        int pos0 = start[b] + slot;
        tt[pos0] = tv;
        ii[pos0] = tid;
        BAR256();
        // deterministic final rank within bucket (t desc, idx asc tiebreak)
        float mt = tt[tid];
        int   mi = ii[tid];
        int b2   = 255 - min(255, max(0, (int)(mt * 256.0f)));
        int bs   = start[b2];
        int m    = hist[b2];
        int rk   = 0;
        for (int qq = 0; qq < m; qq++) {
            float ot = tt[bs + qq];
            int   oi = ii[bs + qq];
            rk += ((ot > mt) || (ot == mt && oi < mi)) ? 1 : 0;
        }
        st_s[bs + rk]   = mt;
        sidx[bs + rk]   = mi;
        sval_s[bs + rk] = (sc[mi] == 0) ? srisk[mi] : 1.0f;
        BAR256();

        // inclusive prefix sum of sorted e
        float x = se[sidx[tid]];
        #pragma unroll
        for (int off = 1; off < 32; off <<= 1) {
            float n = __shfl_up_sync(0xffffffffu, x, off);
            if (lane >= off) x += n;
        }
        if (lane == 31) wpart[wid] = x;
        BAR256();
        float woff = 0.f;
        for (int w = 0; w < wid; w++) woff += wpart[w];
        float pref = x + woff;

        g_tsrt[blk * RPB + tid] = st_s[tid];
        g_pe[blk * RPB + tid]   = pref;
    }

    grid_bar();    // single global sync: all chunks published

    // ================= Phase C: conflict-free layout ==========
    // warp = (grp, 32 consecutive sorted queries); grp owns 8 chunks.
    // Lanes probe the SAME chunk at monotone, clustered positions ->
    // broadcast / consecutive banks (no crossbar serialization).
    #pragma unroll
    for (int u = 0; u < NB / (4 * NT); u++) {
        int i4 = tid + u * NT;
        float4 g = __ldcg(&((const float4*)g_tsrt)[i4]);
        int base = i4 * 4;
        float* dst = &t_tab[(base >> 8) * TPAD + (base & 255)];
        dst[0] = g.x; dst[1] = g.y; dst[2] = g.z; dst[3] = g.w;
    }
    __syncthreads();

    const int grp = tid >> 8;        // 0..3 -> chunks grp*8 .. grp*8+7
    const int q   = tid & 255;       // sorted query position in own chunk
    const float ti = st_s[q];

    int cw[8];
    #pragma unroll
    for (int k = 0; k < 8; k++) cw[k] = 0;
    #pragma unroll
    for (int s = CHK / 2; s > 0; s >>= 1) {
        #pragma unroll
        for (int k = 0; k < 8; k++)
            cw[k] += (t_tab[(grp * 8 + k) * TPAD + cw[k] + s - 1] > ti) ? s : 0;
    }
    #pragma unroll
    for (int k = 0; k < 8; k++)
        cw[k] += (t_tab[(grp * 8 + k) * TPAD + cw[k]] > ti) ? 1 : 0;

    float psum = 0.f;
    int   pcnt = 0;
    #pragma unroll
    for (int k = 0; k < 8; k++) {
        if (cw[k] > 0) {
            psum += __ldcg(&g_pe[(grp * 8 + k) * CHK + cw[k] - 1]);
            pcnt += cw[k];
        }
    }
    sq_sum[tid] = psum;
    sq_cnt[tid] = pcnt;
    __syncthreads();

    float per = 0.f;
    int   cv  = 0;
    if (tid < 256) {
        float sum = sq_sum[tid] + sq_sum[tid + 256]
                  + sq_sum[tid + 512] + sq_sum[tid + 768];
        int   cnt = sq_cnt[tid] + sq_cnt[tid + 256]
                  + sq_cnt[tid + 512] + sq_cnt[tid + 768];
        float v = sval_s[tid];        // risk (<0) if c==0, else +1 sentinel
        if (v < 0.5f && cnt > 0) {
            per = __logf(sum) - v;
            cv  = 1;
        }
    }

    #pragma unroll
    for (int off = 16; off > 0; off >>= 1) {
        per += __shfl_xor_sync(0xffffffffu, per, off);
        cv  += __shfl_xor_sync(0xffffffffu, cv, off);
    }
    if (lane == 0) { bredf[wid] = per; bredi[wid] = cv; }
    __syncthreads();
    if (wid == 0) {
        float p2 = bredf[lane];
        int   c2 = bredi[lane];
        #pragma unroll
        for (int off = 16; off > 0; off >>= 1) {
            p2 += __shfl_xor_sync(0xffffffffu, p2, off);
            c2 += __shfl_xor_sync(0xffffffffu, c2, off);
        }
        int last = 0;
        if (lane == 0) {
            g_per[blk] = p2;
            g_cnt[blk] = c2;
            __threadfence();
            int tk = atomicAdd(&g_ticket, 1);
            last = (tk == GRID - 1) ? 1 : 0;
        }
        last = __shfl_sync(0xffffffffu, last, 0);

        if (last) {    // warp-parallel finalize: lane b handles block b
            __threadfence();
            float pv  = __ldcg(&g_per[lane]);
            int   cvv = __ldcg(&g_cnt[lane]);
            float nv  = __ldcg(&g_nll[lane]);
            #pragma unroll
            for (int off = 16; off > 0; off >>= 1) {
                pv  += __shfl_xor_sync(0xffffffffu, pv, off);
                cvv += __shfl_xor_sync(0xffffffffu, cvv, off);
                nv  += __shfl_xor_sync(0xffffffffu, nv, off);
            }
            if (lane == 0) {
                float rank = (cvv > 0) ? (pv / (float)cvv) : 0.f;
                out[0] = nv / (float)NB + 0.5f * rank;
                g_ticket = 0;   // self-reset for graph replay
            }
        }
    }
}

extern "C" void kernel_launch(void* const* d_in, const int* in_sizes, int n_in,
                              void* d_out, int out_size)
{
    const float* outputs = (const float*)d_in[0];
    const int*   y       = (const int*)d_in[1];
    const float* t       = (const float*)d_in[2];
    const int*   c       = (const int*)d_in[3];
    float*       out     = (float*)d_out;

    surv_one_kernel<<<GRID, NT>>>(outputs, y, t, c, out);
}